// round 1
// baseline (speedup 1.0000x reference)
#include <cuda_runtime.h>
#include <math.h>

#define Bn 8
#define Tn 2048
#define Cn 1024
#define Hn 256
#define Mn (Bn * Tn)   // 16384

// Scratch for Q, K, V projections (allocation-free rule: __device__ globals)
__device__ float g_Q[Mn * Hn];
__device__ float g_K[Mn * Hn];
__device__ float g_V[Mn * Hn];

// ---------------------------------------------------------------------------
// Projection GEMM: out[m,n] = sum_k x[m,k] * W[k,n]
// M=16384, K=1024, N=256.  BM=64, BN=64, BK=32, 256 threads, 4x4 per thread.
// grid.z selects which of Wq/Wk/Wv -> g_Q/g_K/g_V.
// ---------------------------------------------------------------------------
__global__ void proj_kernel(const float* __restrict__ x,
                            const float* __restrict__ Wq,
                            const float* __restrict__ Wk,
                            const float* __restrict__ Wv) {
    __shared__ float As[32][68];   // As[k][m], padded
    __shared__ float Bs[32][68];   // Bs[k][n], padded

    const float* W  = (blockIdx.z == 0) ? Wq : (blockIdx.z == 1 ? Wk : Wv);
    float*       out = (blockIdx.z == 0) ? g_Q : (blockIdx.z == 1 ? g_K : g_V);

    const int m0 = blockIdx.y * 64;
    const int n0 = blockIdx.x * 64;
    const int tid = threadIdx.x;
    const int tx = tid & 15;        // 0..15 -> n
    const int ty = tid >> 4;        // 0..15 -> m

    float acc[4][4];
    #pragma unroll
    for (int i = 0; i < 4; i++)
        #pragma unroll
        for (int j = 0; j < 4; j++) acc[i][j] = 0.f;

    for (int k0 = 0; k0 < Cn; k0 += 32) {
        // Load A tile (64 rows x 32 k), store transposed As[k][m]
        #pragma unroll
        for (int t = tid; t < 512; t += 256) {
            int m  = t >> 3;            // 8 float4 per row
            int kk = (t & 7) * 4;
            float4 v = *(const float4*)&x[(size_t)(m0 + m) * Cn + k0 + kk];
            As[kk + 0][m] = v.x;
            As[kk + 1][m] = v.y;
            As[kk + 2][m] = v.z;
            As[kk + 3][m] = v.w;
        }
        // Load B tile (32 k x 64 n)
        #pragma unroll
        for (int t = tid; t < 512; t += 256) {
            int kk = t >> 4;            // 16 float4 per row of 64
            int n  = (t & 15) * 4;
            float4 v = *(const float4*)&W[(size_t)(k0 + kk) * Hn + n0 + n];
            Bs[kk][n + 0] = v.x;
            Bs[kk][n + 1] = v.y;
            Bs[kk][n + 2] = v.z;
            Bs[kk][n + 3] = v.w;
        }
        __syncthreads();

        #pragma unroll
        for (int k = 0; k < 32; k++) {
            float a[4], b[4];
            #pragma unroll
            for (int i = 0; i < 4; i++) a[i] = As[k][ty * 4 + i];
            #pragma unroll
            for (int j = 0; j < 4; j++) b[j] = Bs[k][tx * 4 + j];
            #pragma unroll
            for (int i = 0; i < 4; i++)
                #pragma unroll
                for (int j = 0; j < 4; j++)
                    acc[i][j] += a[i] * b[j];
        }
        __syncthreads();
    }

    #pragma unroll
    for (int i = 0; i < 4; i++) {
        float4 v = make_float4(acc[i][0], acc[i][1], acc[i][2], acc[i][3]);
        *(float4*)&out[(size_t)(m0 + ty * 4 + i) * Hn + n0 + tx * 4] = v;
    }
}

// ---------------------------------------------------------------------------
// Causal flash attention.
// BLOCK_M=64 query rows per CTA, 256 threads: thread t owns row (t>>2),
// dim quarter (t&3)*64..+63.  K/V tiles of 32 rows staged in 64KB smem.
// Online softmax; tiles fully above the diagonal are skipped by the loop bound.
// ---------------------------------------------------------------------------
__global__ void attn_kernel(float* __restrict__ out) {
    extern __shared__ float smem[];
    float* Ksm = smem;              // 32*256 floats
    float* Vsm = smem + 32 * 256;   // 32*256 floats

    const int b   = blockIdx.y;
    const int m0  = blockIdx.x * 64;
    const int tid = threadIdx.x;
    const int r   = tid >> 2;       // 0..63 row within tile
    const int qq  = tid & 3;        // dim quarter
    const int row_g = m0 + r;

    const float* Qb = g_Q + (size_t)b * Tn * Hn;
    const float* Kb = g_K + (size_t)b * Tn * Hn;
    const float* Vb = g_V + (size_t)b * Tn * Hn;

    float4 qreg[16];
    {
        const float4* qp = (const float4*)&Qb[(size_t)row_g * Hn + qq * 64];
        #pragma unroll
        for (int i = 0; i < 16; i++) qreg[i] = qp[i];
    }

    float4 acc[16];
    #pragma unroll
    for (int i = 0; i < 16; i++) acc[i] = make_float4(0.f, 0.f, 0.f, 0.f);
    float m_run = -INFINITY, l_run = 0.f;
    const float scale = 0.0625f;    // 1/sqrt(256)

    const int kv_end = m0 + 64;     // causal: no keys beyond last row of this tile
    for (int kv0 = 0; kv0 < kv_end; kv0 += 32) {
        // Stage K,V tiles (contiguous 32*256 floats each = 2048 float4)
        const float4* Kg = (const float4*)(Kb + (size_t)kv0 * Hn);
        const float4* Vg = (const float4*)(Vb + (size_t)kv0 * Hn);
        float4* Ks4 = (float4*)Ksm;
        float4* Vs4 = (float4*)Vsm;
        #pragma unroll
        for (int t = 0; t < 8; t++) {
            Ks4[tid + t * 256] = Kg[tid + t * 256];
            Vs4[tid + t * 256] = Vg[tid + t * 256];
        }
        __syncthreads();

        // Scores: each thread partial over its 64 dims, reduce across 4 lanes
        float s[32];
        #pragma unroll
        for (int j = 0; j < 32; j++) {
            const float4* kr = (const float4*)&Ksm[j * 256 + qq * 64];
            float sx = 0.f, sy = 0.f, sz = 0.f, sw = 0.f;
            #pragma unroll
            for (int i = 0; i < 16; i++) {
                float4 kv = kr[i];
                sx += qreg[i].x * kv.x;
                sy += qreg[i].y * kv.y;
                sz += qreg[i].z * kv.z;
                sw += qreg[i].w * kv.w;
            }
            float sj = (sx + sy) + (sz + sw);
            sj += __shfl_xor_sync(0xffffffffu, sj, 1);
            sj += __shfl_xor_sync(0xffffffffu, sj, 2);
            s[j] = sj;
        }

        // Causal mask + online softmax update
        float mx = -INFINITY;
        #pragma unroll
        for (int j = 0; j < 32; j++) {
            int kj = kv0 + j;
            s[j] = (kj <= row_g) ? s[j] * scale : -INFINITY;
            mx = fmaxf(mx, s[j]);
        }
        float m_new = fmaxf(m_run, mx);
        float alpha = __expf(m_run - m_new);   // 0 on first tile (m_run=-inf)
        float psum = 0.f;
        #pragma unroll
        for (int j = 0; j < 32; j++) {
            s[j] = __expf(s[j] - m_new);       // exp(-inf)=0 handles mask
            psum += s[j];
        }
        l_run = l_run * alpha + psum;
        m_run = m_new;

        #pragma unroll
        for (int i = 0; i < 16; i++) {
            acc[i].x *= alpha; acc[i].y *= alpha;
            acc[i].z *= alpha; acc[i].w *= alpha;
        }
        #pragma unroll
        for (int j = 0; j < 32; j++) {
            float p = s[j];
            const float4* vr = (const float4*)&Vsm[j * 256 + qq * 64];
            #pragma unroll
            for (int i = 0; i < 16; i++) {
                float4 vv = vr[i];
                acc[i].x += p * vv.x;
                acc[i].y += p * vv.y;
                acc[i].z += p * vv.z;
                acc[i].w += p * vv.w;
            }
        }
        __syncthreads();
    }

    const float inv_l = 1.f / l_run;
    float4* op = (float4*)&out[((size_t)b * Tn + row_g) * Hn + qq * 64];
    #pragma unroll
    for (int i = 0; i < 16; i++) {
        float4 a = acc[i];
        op[i] = make_float4(a.x * inv_l, a.y * inv_l, a.z * inv_l, a.w * inv_l);
    }
}

extern "C" void kernel_launch(void* const* d_in, const int* in_sizes, int n_in,
                              void* d_out, int out_size) {
    const float* x  = (const float*)d_in[0];
    const float* Wq = (const float*)d_in[1];
    const float* Wk = (const float*)d_in[2];
    const float* Wv = (const float*)d_in[3];
    float* out = (float*)d_out;

    // QKV projections: grid (N/64=4, M/64=256, 3)
    dim3 pgrid(Hn / 64, Mn / 64, 3);
    proj_kernel<<<pgrid, 256>>>(x, Wq, Wk, Wv);

    // Attention: grid (T/64=32, B=8), 64KB dynamic smem
    cudaFuncSetAttribute(attn_kernel,
                         cudaFuncAttributeMaxDynamicSharedMemorySize, 64 * 1024);
    attn_kernel<<<dim3(Tn / 64, Bn), 256, 64 * 1024>>>(out);
}

// round 2
// speedup vs baseline: 3.3060x; 3.3060x over previous
#include <cuda_runtime.h>
#include <math.h>

#define Bn 8
#define Tn 2048
#define Cn 1024
#define Hn 256
#define Mn (Bn * Tn)   // 16384

// Scratch for Q, K, V projections (allocation-free rule: __device__ globals)
__device__ float g_Q[Mn * Hn];
__device__ float g_K[Mn * Hn];
__device__ float g_V[Mn * Hn];

// ---------------------------------------------------------------------------
// Projection GEMM: out[m,n] = sum_k x[m,k] * W[k,n]
// M=16384, K=1024, N=256.  BM=128, BN=128, BK=16, 256 threads, 8x8 per thread.
// grid.z selects which of Wq/Wk/Wv -> g_Q/g_K/g_V.
// Thread (tx,ty): rows m0+ty*8..+7, cols {n0+tx*4..+3} and {n0+64+tx*4..+3}.
// ---------------------------------------------------------------------------
__global__ __launch_bounds__(256, 2)
void proj_kernel(const float* __restrict__ x,
                 const float* __restrict__ Wq,
                 const float* __restrict__ Wk,
                 const float* __restrict__ Wv) {
    __shared__ float As[16][132];   // As[k][m], padded
    __shared__ float Bs[16][128];   // Bs[k][n]

    const float* W   = (blockIdx.z == 0) ? Wq : (blockIdx.z == 1 ? Wk : Wv);
    float*       out = (blockIdx.z == 0) ? g_Q : (blockIdx.z == 1 ? g_K : g_V);

    const int m0 = blockIdx.y * 128;
    const int n0 = blockIdx.x * 128;
    const int tid = threadIdx.x;
    const int tx = tid & 15;        // 0..15 -> n group
    const int ty = tid >> 4;        // 0..15 -> m group

    float acc[8][8];
    #pragma unroll
    for (int i = 0; i < 8; i++)
        #pragma unroll
        for (int j = 0; j < 8; j++) acc[i][j] = 0.f;

    for (int k0 = 0; k0 < Cn; k0 += 16) {
        // A tile: 128 rows x 16 k = 512 float4; store transposed As[k][m]
        #pragma unroll
        for (int f = tid; f < 512; f += 256) {
            int m  = f >> 2;            // 4 float4 per row (16 k)
            int kk = (f & 3) * 4;
            float4 v = *(const float4*)&x[(size_t)(m0 + m) * Cn + k0 + kk];
            As[kk + 0][m] = v.x;
            As[kk + 1][m] = v.y;
            As[kk + 2][m] = v.z;
            As[kk + 3][m] = v.w;
        }
        // B tile: 16 k x 128 n = 512 float4
        #pragma unroll
        for (int f = tid; f < 512; f += 256) {
            int kk = f >> 5;            // 32 float4 per row of 128
            int n  = (f & 31) * 4;
            *(float4*)&Bs[kk][n] = *(const float4*)&W[(size_t)(k0 + kk) * Hn + n0 + n];
        }
        __syncthreads();

        #pragma unroll
        for (int k = 0; k < 16; k++) {
            float4 a0 = *(const float4*)&As[k][ty * 8];
            float4 a1 = *(const float4*)&As[k][ty * 8 + 4];
            float4 b0 = *(const float4*)&Bs[k][tx * 4];
            float4 b1 = *(const float4*)&Bs[k][64 + tx * 4];
            float a[8] = {a0.x, a0.y, a0.z, a0.w, a1.x, a1.y, a1.z, a1.w};
            float b[8] = {b0.x, b0.y, b0.z, b0.w, b1.x, b1.y, b1.z, b1.w};
            #pragma unroll
            for (int i = 0; i < 8; i++)
                #pragma unroll
                for (int j = 0; j < 8; j++)
                    acc[i][j] += a[i] * b[j];
        }
        __syncthreads();
    }

    #pragma unroll
    for (int i = 0; i < 8; i++) {
        float* orow = &out[(size_t)(m0 + ty * 8 + i) * Hn + n0];
        *(float4*)&orow[tx * 4]      = make_float4(acc[i][0], acc[i][1], acc[i][2], acc[i][3]);
        *(float4*)&orow[64 + tx * 4] = make_float4(acc[i][4], acc[i][5], acc[i][6], acc[i][7]);
    }
}

// ---------------------------------------------------------------------------
// Causal flash attention.
// BLOCK_M=32 query rows per CTA, 256 threads: thread t owns row (t>>3) and
// float4 dim-chunks {qq, qq+8, ..., qq+56} where qq=(t&7). The interleaved
// chunk ownership makes all smem score/PV loads bank-conflict-free
// (bank group = qq, distinct across the 8 lanes sharing a row).
// K/V tiles of 32 rows staged through 64KB smem; online softmax; causal
// tile-skipping via the loop bound. CTA order reversed: heavy tiles first.
// ---------------------------------------------------------------------------
__global__ __launch_bounds__(256, 2)
void attn_kernel(float* __restrict__ out) {
    extern __shared__ float smem[];
    float* Ksm = smem;              // 32*256 floats = 32KB
    float* Vsm = smem + 32 * 256;   // 32*256 floats = 32KB

    const int b   = blockIdx.y;
    const int m0  = ((int)gridDim.x - 1 - (int)blockIdx.x) * 32;
    const int tid = threadIdx.x;
    const int r   = tid >> 3;       // 0..31 row within tile
    const int qq  = tid & 7;        // dim-chunk phase
    const int row_g = m0 + r;

    const float* Qb = g_Q + (size_t)b * Tn * Hn;
    const float* Kb = g_K + (size_t)b * Tn * Hn;
    const float* Vb = g_V + (size_t)b * Tn * Hn;

    const float scale = 0.0625f;    // 1/sqrt(256)

    float4 q[8];
    {
        const float4* qp = (const float4*)&Qb[(size_t)row_g * Hn];
        #pragma unroll
        for (int i = 0; i < 8; i++) {
            float4 v = qp[qq + 8 * i];
            q[i] = make_float4(v.x * scale, v.y * scale, v.z * scale, v.w * scale);
        }
    }

    float4 acc[8];
    #pragma unroll
    for (int i = 0; i < 8; i++) acc[i] = make_float4(0.f, 0.f, 0.f, 0.f);
    float m_run = -INFINITY, l_run = 0.f;

    const int kv_end = m0 + 32;     // causal bound
    for (int kv0 = 0; kv0 < kv_end; kv0 += 32) {
        // Stage K,V tiles (each 32*256 floats = 2048 float4)
        {
            const float4* Kg = (const float4*)(Kb + (size_t)kv0 * Hn);
            const float4* Vg = (const float4*)(Vb + (size_t)kv0 * Hn);
            float4* Ks4 = (float4*)Ksm;
            float4* Vs4 = (float4*)Vsm;
            #pragma unroll
            for (int t = 0; t < 8; t++) {
                Ks4[tid + t * 256] = Kg[tid + t * 256];
                Vs4[tid + t * 256] = Vg[tid + t * 256];
            }
        }
        __syncthreads();

        // Scores: partial dot over this thread's 32 dims, reduce across 8 lanes
        float s[32];
        #pragma unroll
        for (int j = 0; j < 32; j++) {
            const float4* kr = (const float4*)Ksm + j * 64;
            float sx = 0.f, sy = 0.f, sz = 0.f, sw = 0.f;
            #pragma unroll
            for (int i = 0; i < 8; i++) {
                float4 kv = kr[qq + 8 * i];
                sx += q[i].x * kv.x;
                sy += q[i].y * kv.y;
                sz += q[i].z * kv.z;
                sw += q[i].w * kv.w;
            }
            float sj = (sx + sy) + (sz + sw);
            sj += __shfl_xor_sync(0xffffffffu, sj, 1);
            sj += __shfl_xor_sync(0xffffffffu, sj, 2);
            sj += __shfl_xor_sync(0xffffffffu, sj, 4);
            s[j] = sj;
        }

        // Causal mask + online softmax update (scale pre-folded into q)
        float mx = -INFINITY;
        #pragma unroll
        for (int j = 0; j < 32; j++) {
            s[j] = (kv0 + j <= row_g) ? s[j] : -INFINITY;
            mx = fmaxf(mx, s[j]);
        }
        float m_new = fmaxf(m_run, mx);
        float alpha = __expf(m_run - m_new);   // 0 on first tile
        float psum = 0.f;
        #pragma unroll
        for (int j = 0; j < 32; j++) {
            s[j] = __expf(s[j] - m_new);       // exp(-inf)=0 handles mask
            psum += s[j];
        }
        l_run = l_run * alpha + psum;
        m_run = m_new;

        #pragma unroll
        for (int i = 0; i < 8; i++) {
            acc[i].x *= alpha; acc[i].y *= alpha;
            acc[i].z *= alpha; acc[i].w *= alpha;
        }
        #pragma unroll
        for (int j = 0; j < 32; j++) {
            float p = s[j];
            const float4* vr = (const float4*)Vsm + j * 64;
            #pragma unroll
            for (int i = 0; i < 8; i++) {
                float4 vv = vr[qq + 8 * i];
                acc[i].x += p * vv.x;
                acc[i].y += p * vv.y;
                acc[i].z += p * vv.z;
                acc[i].w += p * vv.w;
            }
        }
        __syncthreads();
    }

    const float inv_l = 1.f / l_run;
    float4* op = (float4*)&out[((size_t)b * Tn + row_g) * Hn];
    #pragma unroll
    for (int i = 0; i < 8; i++) {
        float4 a = acc[i];
        op[qq + 8 * i] = make_float4(a.x * inv_l, a.y * inv_l, a.z * inv_l, a.w * inv_l);
    }
}

extern "C" void kernel_launch(void* const* d_in, const int* in_sizes, int n_in,
                              void* d_out, int out_size) {
    const float* x  = (const float*)d_in[0];
    const float* Wq = (const float*)d_in[1];
    const float* Wk = (const float*)d_in[2];
    const float* Wv = (const float*)d_in[3];
    float* out = (float*)d_out;

    // QKV projections: grid (N/128=2, M/128=128, 3)
    dim3 pgrid(Hn / 128, Mn / 128, 3);
    proj_kernel<<<pgrid, 256>>>(x, Wq, Wk, Wv);

    // Attention: grid (T/32=64, B=8), 64KB dynamic smem
    cudaFuncSetAttribute(attn_kernel,
                         cudaFuncAttributeMaxDynamicSharedMemorySize, 64 * 1024);
    attn_kernel<<<dim3(Tn / 32, Bn), 256, 64 * 1024>>>(out);
}

// round 3
// speedup vs baseline: 5.1824x; 1.5676x over previous
#include <cuda_runtime.h>
#include <math.h>

#define Bn 8
#define Tn 2048
#define Cn 1024
#define Hn 256
#define Mn (Bn * Tn)   // 16384

// Scratch (allocation-free rule: __device__ globals)
__device__ float g_Q[Mn * Hn];
__device__ float g_K[Mn * Hn];
__device__ float g_V[Mn * Hn];
__device__ float g_Qt[Mn * Hn];   // [b][dim][T] transposed
__device__ float g_Kt[Mn * Hn];   // [b][dim][T] transposed

// ---------------------------------------------------------------------------
// Projection GEMM: out[m,n] = sum_k x[m,k] * W[k,n]
// M=16384, K=1024, N=256.  BM=128, BN=128, BK=16, 256 threads, 8x8/thread.
// ---------------------------------------------------------------------------
__global__ __launch_bounds__(256, 2)
void proj_kernel(const float* __restrict__ x,
                 const float* __restrict__ Wq,
                 const float* __restrict__ Wk,
                 const float* __restrict__ Wv) {
    __shared__ float As[16][132];   // As[k][m], padded
    __shared__ float Bs[16][128];   // Bs[k][n]

    const float* W   = (blockIdx.z == 0) ? Wq : (blockIdx.z == 1 ? Wk : Wv);
    float*       out = (blockIdx.z == 0) ? g_Q : (blockIdx.z == 1 ? g_K : g_V);

    const int m0 = blockIdx.y * 128;
    const int n0 = blockIdx.x * 128;
    const int tid = threadIdx.x;
    const int tx = tid & 15;
    const int ty = tid >> 4;

    float acc[8][8];
    #pragma unroll
    for (int i = 0; i < 8; i++)
        #pragma unroll
        for (int j = 0; j < 8; j++) acc[i][j] = 0.f;

    for (int k0 = 0; k0 < Cn; k0 += 16) {
        #pragma unroll
        for (int f = tid; f < 512; f += 256) {
            int m  = f >> 2;
            int kk = (f & 3) * 4;
            float4 v = *(const float4*)&x[(size_t)(m0 + m) * Cn + k0 + kk];
            As[kk + 0][m] = v.x;
            As[kk + 1][m] = v.y;
            As[kk + 2][m] = v.z;
            As[kk + 3][m] = v.w;
        }
        #pragma unroll
        for (int f = tid; f < 512; f += 256) {
            int kk = f >> 5;
            int n  = (f & 31) * 4;
            *(float4*)&Bs[kk][n] = *(const float4*)&W[(size_t)(k0 + kk) * Hn + n0 + n];
        }
        __syncthreads();

        #pragma unroll
        for (int k = 0; k < 16; k++) {
            float4 a0 = *(const float4*)&As[k][ty * 8];
            float4 a1 = *(const float4*)&As[k][ty * 8 + 4];
            float4 b0 = *(const float4*)&Bs[k][tx * 4];
            float4 b1 = *(const float4*)&Bs[k][64 + tx * 4];
            float a[8] = {a0.x, a0.y, a0.z, a0.w, a1.x, a1.y, a1.z, a1.w};
            float b[8] = {b0.x, b0.y, b0.z, b0.w, b1.x, b1.y, b1.z, b1.w};
            #pragma unroll
            for (int i = 0; i < 8; i++)
                #pragma unroll
                for (int j = 0; j < 8; j++)
                    acc[i][j] += a[i] * b[j];
        }
        __syncthreads();
    }

    #pragma unroll
    for (int i = 0; i < 8; i++) {
        float* orow = &out[(size_t)(m0 + ty * 8 + i) * Hn + n0];
        *(float4*)&orow[tx * 4]      = make_float4(acc[i][0], acc[i][1], acc[i][2], acc[i][3]);
        *(float4*)&orow[64 + tx * 4] = make_float4(acc[i][4], acc[i][5], acc[i][6], acc[i][7]);
    }
}

// ---------------------------------------------------------------------------
// Transpose Q and K:  [b][T][H] -> [b][H][T].  32x32 tiles, block (32,8).
// grid.z = b*2 + which (0=Q, 1=K)
// ---------------------------------------------------------------------------
__global__ __launch_bounds__(256)
void transpose_qk_kernel() {
    __shared__ float tile[32][33];
    const int which = blockIdx.z & 1;
    const int b     = blockIdx.z >> 1;
    const float* src = (which ? g_K : g_Q) + (size_t)b * Tn * Hn;
    float*       dst = (which ? g_Kt : g_Qt) + (size_t)b * Hn * Tn;

    const int t0 = blockIdx.x * 32;
    const int d0 = blockIdx.y * 32;
    const int tx = threadIdx.x;
    const int ty = threadIdx.y;

    #pragma unroll
    for (int i = 0; i < 4; i++)
        tile[ty + 8 * i][tx] = src[(size_t)(t0 + ty + 8 * i) * Hn + d0 + tx];
    __syncthreads();
    #pragma unroll
    for (int i = 0; i < 4; i++)
        dst[(size_t)(d0 + ty + 8 * i) * Tn + t0 + tx] = tile[tx][ty + 8 * i];
}

// ---------------------------------------------------------------------------
// Causal flash attention, GEMM-blocked.
// BLOCK_M=64 queries, BLOCK_N=64 keys/tile, 256 threads (tx 0..15, ty 0..15).
// S-GEMM: thread computes 4 rows (ty*4..) x 4 keys (tx*4..), k-major Q/K smem.
// PV-GEMM: thread computes 4 rows x 16 dims (chunks tx, tx+16, tx+32, tx+48).
// Online softmax state per thread for its 4 rows (replicated across tx lanes).
// ---------------------------------------------------------------------------
__global__ __launch_bounds__(256, 1)
void attn_kernel(float* __restrict__ out) {
    extern __shared__ float smem[];
    float* Qs = smem;               // [256][64]  k-major
    float* Ks = Qs + 256 * 64;      // [256][64]  k-major
    float* Vs = Ks + 256 * 64;      // [64][256]  natural
    float* Ps = Vs + 64 * 256;      // [64][68]   Ps[key][row]

    const int b   = blockIdx.y;
    const int m0  = ((int)gridDim.x - 1 - (int)blockIdx.x) * 64;
    const int tid = threadIdx.x;
    const int tx  = tid & 15;
    const int ty  = tid >> 4;

    const float* Qt = g_Qt + (size_t)b * Hn * Tn;
    const float* Kt = g_Kt + (size_t)b * Hn * Tn;
    const float* Vb = g_V  + (size_t)b * Tn * Hn;

    const float scale = 0.0625f;    // 1/sqrt(256), folded into Q

    // Load Q tile (k-major, coalesced, conflict-free): Qs[k][m] = Qt[k][m0+m]*scale
    #pragma unroll
    for (int it = 0; it < 16; it++) {
        int f  = tid + it * 256;
        int k  = f >> 4;
        int m4 = (f & 15) << 2;
        float4 v = *(const float4*)&Qt[(size_t)k * Tn + m0 + m4];
        v.x *= scale; v.y *= scale; v.z *= scale; v.w *= scale;
        *(float4*)&Qs[k * 64 + m4] = v;
    }

    float4 o[4][4];
    #pragma unroll
    for (int i = 0; i < 4; i++)
        #pragma unroll
        for (int c = 0; c < 4; c++) o[i][c] = make_float4(0.f, 0.f, 0.f, 0.f);
    float m_run[4], l_run[4];
    #pragma unroll
    for (int i = 0; i < 4; i++) { m_run[i] = -INFINITY; l_run[i] = 0.f; }

    const int rowg = m0 + ty * 4;

    for (int kv0 = 0; kv0 <= m0; kv0 += 64) {
        // ---- stage K (k-major) and V (natural) tiles ----
        __syncthreads();   // prev tile's smem reads complete
        #pragma unroll
        for (int it = 0; it < 16; it++) {
            int f  = tid + it * 256;
            int k  = f >> 4;
            int m4 = (f & 15) << 2;
            *(float4*)&Ks[k * 64 + m4] =
                *(const float4*)&Kt[(size_t)k * Tn + kv0 + m4];
        }
        #pragma unroll
        for (int it = 0; it < 16; it++) {
            int f  = tid + it * 256;
            int r  = f >> 6;
            int d4 = (f & 63) << 2;
            *(float4*)&Vs[r * 256 + d4] =
                *(const float4*)&Vb[(size_t)(kv0 + r) * Hn + d4];
        }
        __syncthreads();

        // ---- S = Q K^T  (4x4 register block) ----
        float s[4][4];
        #pragma unroll
        for (int i = 0; i < 4; i++)
            #pragma unroll
            for (int j = 0; j < 4; j++) s[i][j] = 0.f;

        #pragma unroll 4
        for (int k = 0; k < 256; k++) {
            float4 aq = *(const float4*)&Qs[k * 64 + ty * 4];
            float4 bq = *(const float4*)&Ks[k * 64 + tx * 4];
            float a[4] = {aq.x, aq.y, aq.z, aq.w};
            float bb[4] = {bq.x, bq.y, bq.z, bq.w};
            #pragma unroll
            for (int i = 0; i < 4; i++)
                #pragma unroll
                for (int j = 0; j < 4; j++)
                    s[i][j] += a[i] * bb[j];
        }

        // ---- causal mask ----
        const int keyg = kv0 + tx * 4;
        #pragma unroll
        for (int i = 0; i < 4; i++)
            #pragma unroll
            for (int j = 0; j < 4; j++)
                if (keyg + j > rowg + i) s[i][j] = -INFINITY;

        // ---- online softmax (row reduction over 16 tx lanes: xor 1,2,4,8) ----
        float alpha[4], psum[4];
        #pragma unroll
        for (int i = 0; i < 4; i++) {
            float mx = fmaxf(fmaxf(s[i][0], s[i][1]), fmaxf(s[i][2], s[i][3]));
            mx = fmaxf(mx, __shfl_xor_sync(0xffffffffu, mx, 1));
            mx = fmaxf(mx, __shfl_xor_sync(0xffffffffu, mx, 2));
            mx = fmaxf(mx, __shfl_xor_sync(0xffffffffu, mx, 4));
            mx = fmaxf(mx, __shfl_xor_sync(0xffffffffu, mx, 8));
            float m_new = fmaxf(m_run[i], mx);
            alpha[i] = __expf(m_run[i] - m_new);
            m_run[i] = m_new;
            float ps = 0.f;
            #pragma unroll
            for (int j = 0; j < 4; j++) {
                s[i][j] = __expf(s[i][j] - m_new);
                ps += s[i][j];
            }
            psum[i] = ps;
        }
        #pragma unroll
        for (int i = 0; i < 4; i++) {
            float ps = psum[i];
            ps += __shfl_xor_sync(0xffffffffu, ps, 1);
            ps += __shfl_xor_sync(0xffffffffu, ps, 2);
            ps += __shfl_xor_sync(0xffffffffu, ps, 4);
            ps += __shfl_xor_sync(0xffffffffu, ps, 8);
            l_run[i] = l_run[i] * alpha[i] + ps;
        }

        // rescale accumulator
        #pragma unroll
        for (int i = 0; i < 4; i++) {
            float al = alpha[i];
            #pragma unroll
            for (int c = 0; c < 4; c++) {
                o[i][c].x *= al; o[i][c].y *= al;
                o[i][c].z *= al; o[i][c].w *= al;
            }
        }

        // write P transposed: Ps[key][row]
        #pragma unroll
        for (int j = 0; j < 4; j++)
            #pragma unroll
            for (int i = 0; i < 4; i++)
                Ps[(tx * 4 + j) * 68 + ty * 4 + i] = s[i][j];
        __syncthreads();

        // ---- O += P V  (4 rows x 16 dims per thread) ----
        #pragma unroll 2
        for (int k = 0; k < 64; k++) {
            float4 pq = *(const float4*)&Ps[k * 68 + ty * 4];
            float p[4] = {pq.x, pq.y, pq.z, pq.w};
            #pragma unroll
            for (int c = 0; c < 4; c++) {
                float4 v = *(const float4*)&Vs[k * 256 + tx * 4 + 64 * c];
                #pragma unroll
                for (int i = 0; i < 4; i++) {
                    o[i][c].x += p[i] * v.x;
                    o[i][c].y += p[i] * v.y;
                    o[i][c].z += p[i] * v.z;
                    o[i][c].w += p[i] * v.w;
                }
            }
        }
    }

    // ---- epilogue ----
    #pragma unroll
    for (int i = 0; i < 4; i++) {
        float inv = 1.f / l_run[i];
        float* orow = &out[((size_t)b * Tn + rowg + i) * Hn];
        #pragma unroll
        for (int c = 0; c < 4; c++) {
            float4 a = o[i][c];
            *(float4*)&orow[tx * 4 + 64 * c] =
                make_float4(a.x * inv, a.y * inv, a.z * inv, a.w * inv);
        }
    }
}

extern "C" void kernel_launch(void* const* d_in, const int* in_sizes, int n_in,
                              void* d_out, int out_size) {
    const float* x  = (const float*)d_in[0];
    const float* Wq = (const float*)d_in[1];
    const float* Wk = (const float*)d_in[2];
    const float* Wv = (const float*)d_in[3];
    float* out = (float*)d_out;

    // QKV projections
    dim3 pgrid(Hn / 128, Mn / 128, 3);
    proj_kernel<<<pgrid, 256>>>(x, Wq, Wk, Wv);

    // Transpose Q,K to [b][H][T]
    transpose_qk_kernel<<<dim3(Tn / 32, Hn / 32, Bn * 2), dim3(32, 8)>>>();

    // Attention: grid (T/64=32, B=8), 214016B dynamic smem
    const int smem_bytes = (256 * 64 * 2 + 64 * 256 + 64 * 68) * 4;
    cudaFuncSetAttribute(attn_kernel,
                         cudaFuncAttributeMaxDynamicSharedMemorySize, smem_bytes);
    attn_kernel<<<dim3(Tn / 64, Bn), 256, smem_bytes>>>(out);
}

// round 5
// speedup vs baseline: 7.1079x; 1.3715x over previous
#include <cuda_runtime.h>
#include <math.h>
#include <cstdint>

#define Bn 8
#define Tn 2048
#define Cn 1024
#define Hn 256
#define Mn (Bn * Tn)   // 16384

// Scratch (allocation-free rule: __device__ globals)
__device__ float g_Q[Mn * Hn];
__device__ float g_K[Mn * Hn];
__device__ float g_V[Mn * Hn];
__device__ float g_Qt[Mn * Hn];      // [b][dim][T]
__device__ float g_Kt[Mn * Hn];      // [b][dim][T]
__device__ float g_Wt[3 * Hn * Cn];  // [which][n][k]  (W transposed, k-major)

// ---------------------------------------------------------------------------
// Helpers
// ---------------------------------------------------------------------------
__device__ __forceinline__ uint32_t smem_u32(const void* p) {
    uint32_t a;
    asm("{ .reg .u64 t; cvta.to.shared.u64 t, %1; cvt.u32.u64 %0, t; }"
        : "=r"(a) : "l"(p));
    return a;
}
__device__ __forceinline__ uint32_t f2tf32(float f) {
    uint32_t u;
    asm("cvt.rna.tf32.f32 %0, %1;" : "=r"(u) : "f"(f));
    return u;
}
__device__ __forceinline__ void cp_async16(uint32_t saddr, const void* g) {
    asm volatile("cp.async.cg.shared.global [%0], [%1], 16;"
                 :: "r"(saddr), "l"(g) : "memory");
}
__device__ __forceinline__ void cp_commit() {
    asm volatile("cp.async.commit_group;" ::: "memory");
}
__device__ __forceinline__ void mma_tf32(float* c, const uint32_t* a, const uint32_t* b) {
    asm volatile(
        "mma.sync.aligned.m16n8k8.row.col.f32.tf32.tf32.f32 "
        "{%0,%1,%2,%3}, {%4,%5,%6,%7}, {%8,%9}, {%0,%1,%2,%3};"
        : "+f"(c[0]), "+f"(c[1]), "+f"(c[2]), "+f"(c[3])
        : "r"(a[0]), "r"(a[1]), "r"(a[2]), "r"(a[3]), "r"(b[0]), "r"(b[1]));
}

// ---------------------------------------------------------------------------
// Transpose W: [K=1024, N=256] -> g_Wt[which][N][K]
// ---------------------------------------------------------------------------
__global__ __launch_bounds__(256)
void transpose_w_kernel(const float* __restrict__ Wq,
                        const float* __restrict__ Wk,
                        const float* __restrict__ Wv) {
    __shared__ float tile[32][33];
    const int which = blockIdx.z;
    const float* W = (which == 0) ? Wq : (which == 1 ? Wk : Wv);
    float* dst = g_Wt + (size_t)which * Hn * Cn;
    const int k0 = blockIdx.x * 32;
    const int n0 = blockIdx.y * 32;
    const int tx = threadIdx.x, ty = threadIdx.y;
    #pragma unroll
    for (int i = 0; i < 4; i++)
        tile[ty + 8 * i][tx] = W[(size_t)(k0 + ty + 8 * i) * Hn + n0 + tx];
    __syncthreads();
    #pragma unroll
    for (int i = 0; i < 4; i++)
        dst[(size_t)(n0 + ty + 8 * i) * Cn + k0 + tx] = tile[tx][ty + 8 * i];
}

// ---------------------------------------------------------------------------
// Projection via mma.sync tf32: out[16384,256] = x[16384,1024] @ W[1024,256]
// CTA 128x128, BK=32, 8 warps (4 M x 2 N), warp tile 32x64 (2x8 m16n8k8).
// Smem rows padded to 36 floats -> conflict-free fragment loads.
// cp.async double-buffered K pipeline.
// ---------------------------------------------------------------------------
#define AROW 36
#define TILE_F (128 * AROW)            // floats per tile buffer
#define TILE_B (TILE_F * 4)            // 18432 bytes
#define PROJ_SMEM (4 * TILE_B)         // A0,A1,B0,B1 = 73728

__global__ __launch_bounds__(256, 2)
void proj_wmma_kernel(const float* __restrict__ x) {
    extern __shared__ char smem[];
    const uint32_t sb = smem_u32(smem);

    const int tid  = threadIdx.x;
    const int warp = tid >> 5, lane = tid & 31;
    const int group = lane >> 2, tig = lane & 3;
    const int wm = warp & 3, wn = warp >> 2;
    const int which = blockIdx.z;
    const int m0 = blockIdx.x * 128, n0 = blockIdx.y * 128;

    const float* A  = x + (size_t)m0 * Cn;
    const float* Bt = g_Wt + (size_t)which * Hn * Cn + (size_t)n0 * Cn;
    float* outp = ((which == 0) ? g_Q : (which == 1 ? g_K : g_V))
                  + (size_t)m0 * Hn + n0;

    const int r0 = tid >> 3;           // 0..31
    const int cc = (tid & 7) * 4;      // 0..28

    // Fill tile t into buffer bsel (A and B, 4 float4 each per thread)
    auto fill = [&](int t, int bsel) {
        const uint32_t aOff = sb + bsel * TILE_B;
        const uint32_t bOff = sb + 2 * TILE_B + bsel * TILE_B;
        #pragma unroll
        for (int it = 0; it < 4; it++) {
            int row = r0 + 32 * it;
            cp_async16(aOff + (uint32_t)(row * AROW + cc) * 4,
                       A + (size_t)row * Cn + t * 32 + cc);
            cp_async16(bOff + (uint32_t)(row * AROW + cc) * 4,
                       Bt + (size_t)row * Cn + t * 32 + cc);
        }
    };

    float acc[2][8][4];
    #pragma unroll
    for (int mt = 0; mt < 2; mt++)
        #pragma unroll
        for (int nt = 0; nt < 8; nt++)
            #pragma unroll
            for (int q = 0; q < 4; q++) acc[mt][nt][q] = 0.f;

    fill(0, 0);
    cp_commit();

    const int NT = Cn / 32;            // 32 tiles
    #pragma unroll 1
    for (int t = 0; t < NT; t++) {
        if (t + 1 < NT) {
            fill(t + 1, (t + 1) & 1);
            cp_commit();
            asm volatile("cp.async.wait_group 1;" ::: "memory");
        } else {
            asm volatile("cp.async.wait_group 0;" ::: "memory");
        }
        __syncthreads();

        const float* As = (const float*)(smem + (t & 1) * TILE_B);
        const float* Bs = (const float*)(smem + 2 * TILE_B + (t & 1) * TILE_B);

        #pragma unroll
        for (int k8 = 0; k8 < 32; k8 += 8) {
            uint32_t a[2][4];
            #pragma unroll
            for (int mt = 0; mt < 2; mt++) {
                int m = wm * 32 + mt * 16 + group;
                a[mt][0] = f2tf32(As[m * AROW + k8 + tig]);
                a[mt][1] = f2tf32(As[(m + 8) * AROW + k8 + tig]);
                a[mt][2] = f2tf32(As[m * AROW + k8 + tig + 4]);
                a[mt][3] = f2tf32(As[(m + 8) * AROW + k8 + tig + 4]);
            }
            uint32_t b[8][2];
            #pragma unroll
            for (int nt = 0; nt < 8; nt++) {
                int n = wn * 64 + nt * 8 + group;
                b[nt][0] = f2tf32(Bs[n * AROW + k8 + tig]);
                b[nt][1] = f2tf32(Bs[n * AROW + k8 + tig + 4]);
            }
            #pragma unroll
            for (int mt = 0; mt < 2; mt++)
                #pragma unroll
                for (int nt = 0; nt < 8; nt++)
                    mma_tf32(acc[mt][nt], a[mt], b[nt]);
        }
        __syncthreads();
    }

    // Epilogue: C fragment -> gmem
    #pragma unroll
    for (int mt = 0; mt < 2; mt++) {
        int m = wm * 32 + mt * 16 + group;
        #pragma unroll
        for (int nt = 0; nt < 8; nt++) {
            int col = wn * 64 + nt * 8 + 2 * tig;
            *(float2*)&outp[(size_t)m * Hn + col] =
                make_float2(acc[mt][nt][0], acc[mt][nt][1]);
            *(float2*)&outp[(size_t)(m + 8) * Hn + col] =
                make_float2(acc[mt][nt][2], acc[mt][nt][3]);
        }
    }
}

// ---------------------------------------------------------------------------
// Transpose Q and K:  [b][T][H] -> [b][H][T]
// ---------------------------------------------------------------------------
__global__ __launch_bounds__(256)
void transpose_qk_kernel() {
    __shared__ float tile[32][33];
    const int which = blockIdx.z & 1;
    const int b     = blockIdx.z >> 1;
    const float* src = (which ? g_K : g_Q) + (size_t)b * Tn * Hn;
    float*       dst = (which ? g_Kt : g_Qt) + (size_t)b * Hn * Tn;
    const int t0 = blockIdx.x * 32;
    const int d0 = blockIdx.y * 32;
    const int tx = threadIdx.x, ty = threadIdx.y;
    #pragma unroll
    for (int i = 0; i < 4; i++)
        tile[ty + 8 * i][tx] = src[(size_t)(t0 + ty + 8 * i) * Hn + d0 + tx];
    __syncthreads();
    #pragma unroll
    for (int i = 0; i < 4; i++)
        dst[(size_t)(d0 + ty + 8 * i) * Tn + t0 + tx] = tile[tx][ty + 8 * i];
}

// ---------------------------------------------------------------------------
// Causal flash attention, GEMM-blocked SIMT (unchanged from R3).
// ---------------------------------------------------------------------------
__global__ __launch_bounds__(256, 1)
void attn_kernel(float* __restrict__ out) {
    extern __shared__ float fsm[];
    float* Qs = fsm;                // [256][64]
    float* Ks = Qs + 256 * 64;      // [256][64]
    float* Vs = Ks + 256 * 64;      // [64][256]
    float* Ps = Vs + 64 * 256;      // [64][68]

    const int b   = blockIdx.y;
    const int m0  = ((int)gridDim.x - 1 - (int)blockIdx.x) * 64;
    const int tid = threadIdx.x;
    const int tx  = tid & 15;
    const int ty  = tid >> 4;

    const float* Qt = g_Qt + (size_t)b * Hn * Tn;
    const float* Kt = g_Kt + (size_t)b * Hn * Tn;
    const float* Vb = g_V  + (size_t)b * Tn * Hn;

    const float scale = 0.0625f;

    #pragma unroll
    for (int it = 0; it < 16; it++) {
        int f  = tid + it * 256;
        int k  = f >> 4;
        int m4 = (f & 15) << 2;
        float4 v = *(const float4*)&Qt[(size_t)k * Tn + m0 + m4];
        v.x *= scale; v.y *= scale; v.z *= scale; v.w *= scale;
        *(float4*)&Qs[k * 64 + m4] = v;
    }

    float4 o[4][4];
    #pragma unroll
    for (int i = 0; i < 4; i++)
        #pragma unroll
        for (int c = 0; c < 4; c++) o[i][c] = make_float4(0.f, 0.f, 0.f, 0.f);
    float m_run[4], l_run[4];
    #pragma unroll
    for (int i = 0; i < 4; i++) { m_run[i] = -INFINITY; l_run[i] = 0.f; }

    const int rowg = m0 + ty * 4;

    for (int kv0 = 0; kv0 <= m0; kv0 += 64) {
        __syncthreads();
        #pragma unroll
        for (int it = 0; it < 16; it++) {
            int f  = tid + it * 256;
            int k  = f >> 4;
            int m4 = (f & 15) << 2;
            *(float4*)&Ks[k * 64 + m4] = *(const float4*)&Kt[(size_t)k * Tn + kv0 + m4];
        }
        #pragma unroll
        for (int it = 0; it < 16; it++) {
            int f  = tid + it * 256;
            int r  = f >> 6;
            int d4 = (f & 63) << 2;
            *(float4*)&Vs[r * 256 + d4] = *(const float4*)&Vb[(size_t)(kv0 + r) * Hn + d4];
        }
        __syncthreads();

        float s[4][4];
        #pragma unroll
        for (int i = 0; i < 4; i++)
            #pragma unroll
            for (int j = 0; j < 4; j++) s[i][j] = 0.f;

        #pragma unroll 4
        for (int k = 0; k < 256; k++) {
            float4 aq = *(const float4*)&Qs[k * 64 + ty * 4];
            float4 bq = *(const float4*)&Ks[k * 64 + tx * 4];
            float a[4] = {aq.x, aq.y, aq.z, aq.w};
            float bb[4] = {bq.x, bq.y, bq.z, bq.w};
            #pragma unroll
            for (int i = 0; i < 4; i++)
                #pragma unroll
                for (int j = 0; j < 4; j++)
                    s[i][j] += a[i] * bb[j];
        }

        const int keyg = kv0 + tx * 4;
        #pragma unroll
        for (int i = 0; i < 4; i++)
            #pragma unroll
            for (int j = 0; j < 4; j++)
                if (keyg + j > rowg + i) s[i][j] = -INFINITY;

        float alpha[4], psum[4];
        #pragma unroll
        for (int i = 0; i < 4; i++) {
            float mx = fmaxf(fmaxf(s[i][0], s[i][1]), fmaxf(s[i][2], s[i][3]));
            mx = fmaxf(mx, __shfl_xor_sync(0xffffffffu, mx, 1));
            mx = fmaxf(mx, __shfl_xor_sync(0xffffffffu, mx, 2));
            mx = fmaxf(mx, __shfl_xor_sync(0xffffffffu, mx, 4));
            mx = fmaxf(mx, __shfl_xor_sync(0xffffffffu, mx, 8));
            float m_new = fmaxf(m_run[i], mx);
            alpha[i] = __expf(m_run[i] - m_new);
            m_run[i] = m_new;
            float ps = 0.f;
            #pragma unroll
            for (int j = 0; j < 4; j++) {
                s[i][j] = __expf(s[i][j] - m_new);
                ps += s[i][j];
            }
            psum[i] = ps;
        }
        #pragma unroll
        for (int i = 0; i < 4; i++) {
            float ps = psum[i];
            ps += __shfl_xor_sync(0xffffffffu, ps, 1);
            ps += __shfl_xor_sync(0xffffffffu, ps, 2);
            ps += __shfl_xor_sync(0xffffffffu, ps, 4);
            ps += __shfl_xor_sync(0xffffffffu, ps, 8);
            l_run[i] = l_run[i] * alpha[i] + ps;
        }

        #pragma unroll
        for (int i = 0; i < 4; i++) {
            float al = alpha[i];
            #pragma unroll
            for (int c = 0; c < 4; c++) {
                o[i][c].x *= al; o[i][c].y *= al;
                o[i][c].z *= al; o[i][c].w *= al;
            }
        }

        #pragma unroll
        for (int j = 0; j < 4; j++)
            #pragma unroll
            for (int i = 0; i < 4; i++)
                Ps[(tx * 4 + j) * 68 + ty * 4 + i] = s[i][j];
        __syncthreads();

        #pragma unroll 2
        for (int k = 0; k < 64; k++) {
            float4 pq = *(const float4*)&Ps[k * 68 + ty * 4];
            float p[4] = {pq.x, pq.y, pq.z, pq.w};
            #pragma unroll
            for (int c = 0; c < 4; c++) {
                float4 v = *(const float4*)&Vs[k * 256 + tx * 4 + 64 * c];
                #pragma unroll
                for (int i = 0; i < 4; i++) {
                    o[i][c].x += p[i] * v.x;
                    o[i][c].y += p[i] * v.y;
                    o[i][c].z += p[i] * v.z;
                    o[i][c].w += p[i] * v.w;
                }
            }
        }
    }

    #pragma unroll
    for (int i = 0; i < 4; i++) {
        float inv = 1.f / l_run[i];
        float* orow = &out[((size_t)b * Tn + rowg + i) * Hn];
        #pragma unroll
        for (int c = 0; c < 4; c++) {
            float4 a = o[i][c];
            *(float4*)&orow[tx * 4 + 64 * c] =
                make_float4(a.x * inv, a.y * inv, a.z * inv, a.w * inv);
        }
    }
}

extern "C" void kernel_launch(void* const* d_in, const int* in_sizes, int n_in,
                              void* d_out, int out_size) {
    const float* x  = (const float*)d_in[0];
    const float* Wq = (const float*)d_in[1];
    const float* Wk = (const float*)d_in[2];
    const float* Wv = (const float*)d_in[3];
    float* out = (float*)d_out;

    // Transpose W -> g_Wt[which][N][K]
    transpose_w_kernel<<<dim3(Cn / 32, Hn / 32, 3), dim3(32, 8)>>>(Wq, Wk, Wv);

    // QKV projection on tensor cores (mma.sync tf32)
    cudaFuncSetAttribute(proj_wmma_kernel,
                         cudaFuncAttributeMaxDynamicSharedMemorySize, PROJ_SMEM);
    proj_wmma_kernel<<<dim3(Mn / 128, Hn / 128, 3), 256, PROJ_SMEM>>>(x);

    // Transpose Q,K to [b][H][T]
    transpose_qk_kernel<<<dim3(Tn / 32, Hn / 32, Bn * 2), dim3(32, 8)>>>();

    // Attention
    const int smem_bytes = (256 * 64 * 2 + 64 * 256 + 64 * 68) * 4;
    cudaFuncSetAttribute(attn_kernel,
                         cudaFuncAttributeMaxDynamicSharedMemorySize, smem_bytes);
    attn_kernel<<<dim3(Tn / 64, Bn), 256, smem_bytes>>>(out);
}

// round 6
// speedup vs baseline: 14.2012x; 1.9979x over previous
#include <cuda_runtime.h>
#include <math.h>
#include <cstdint>

#define Bn 8
#define Tn 2048
#define Cn 1024
#define Hn 256
#define Mn (Bn * Tn)   // 16384

// Scratch (allocation-free rule: __device__ globals)
__device__ float g_Q[Mn * Hn];       // [b][T][H]  (tf32-rounded)
__device__ float g_K[Mn * Hn];       // [b][T][H]  (tf32-rounded)
__device__ float g_V[Mn * Hn];       // [b][T][H]  (tf32-rounded)
__device__ float g_Vt[Mn * Hn];      // [b][H][T]
__device__ float g_Wt[3 * Hn * Cn];  // [which][n][k]

// ---------------------------------------------------------------------------
// Helpers
// ---------------------------------------------------------------------------
__device__ __forceinline__ uint32_t smem_u32(const void* p) {
    uint32_t a;
    asm("{ .reg .u64 t; cvta.to.shared.u64 t, %1; cvt.u32.u64 %0, t; }"
        : "=r"(a) : "l"(p));
    return a;
}
__device__ __forceinline__ uint32_t f2tf32(float f) {
    uint32_t u;
    asm("cvt.rna.tf32.f32 %0, %1;" : "=r"(u) : "f"(f));
    return u;
}
__device__ __forceinline__ void cp_async16(uint32_t saddr, const void* g) {
    asm volatile("cp.async.cg.shared.global [%0], [%1], 16;"
                 :: "r"(saddr), "l"(g) : "memory");
}
__device__ __forceinline__ void cp_commit() {
    asm volatile("cp.async.commit_group;" ::: "memory");
}
__device__ __forceinline__ void mma_tf32(float* c, const uint32_t* a, const uint32_t* b) {
    asm volatile(
        "mma.sync.aligned.m16n8k8.row.col.f32.tf32.tf32.f32 "
        "{%0,%1,%2,%3}, {%4,%5,%6,%7}, {%8,%9}, {%0,%1,%2,%3};"
        : "+f"(c[0]), "+f"(c[1]), "+f"(c[2]), "+f"(c[3])
        : "r"(a[0]), "r"(a[1]), "r"(a[2]), "r"(a[3]), "r"(b[0]), "r"(b[1]));
}

// ---------------------------------------------------------------------------
// Transpose W: [K=1024, N=256] -> g_Wt[which][N][K]
// ---------------------------------------------------------------------------
__global__ __launch_bounds__(256)
void transpose_w_kernel(const float* __restrict__ Wq,
                        const float* __restrict__ Wk,
                        const float* __restrict__ Wv) {
    __shared__ float tile[32][33];
    const int which = blockIdx.z;
    const float* W = (which == 0) ? Wq : (which == 1 ? Wk : Wv);
    float* dst = g_Wt + (size_t)which * Hn * Cn;
    const int k0 = blockIdx.x * 32;
    const int n0 = blockIdx.y * 32;
    const int tx = threadIdx.x, ty = threadIdx.y;
    #pragma unroll
    for (int i = 0; i < 4; i++)
        tile[ty + 8 * i][tx] = W[(size_t)(k0 + ty + 8 * i) * Hn + n0 + tx];
    __syncthreads();
    #pragma unroll
    for (int i = 0; i < 4; i++)
        dst[(size_t)(n0 + ty + 8 * i) * Cn + k0 + tx] = tile[tx][ty + 8 * i];
}

// ---------------------------------------------------------------------------
// Projection via mma.sync tf32; outputs tf32-ROUNDED fp32 (so downstream
// attention MMAs can use the raw bits with no per-fragment cvt).
// ---------------------------------------------------------------------------
#define AROW 36
#define TILE_F (128 * AROW)
#define TILE_B (TILE_F * 4)
#define PROJ_SMEM (4 * TILE_B)

__global__ __launch_bounds__(256, 2)
void proj_wmma_kernel(const float* __restrict__ x) {
    extern __shared__ char smem[];
    const uint32_t sb = smem_u32(smem);

    const int tid  = threadIdx.x;
    const int warp = tid >> 5, lane = tid & 31;
    const int group = lane >> 2, tig = lane & 3;
    const int wm = warp & 3, wn = warp >> 2;
    const int which = blockIdx.z;
    const int m0 = blockIdx.x * 128, n0 = blockIdx.y * 128;

    const float* A  = x + (size_t)m0 * Cn;
    const float* Bt = g_Wt + (size_t)which * Hn * Cn + (size_t)n0 * Cn;
    float* outp = ((which == 0) ? g_Q : (which == 1 ? g_K : g_V))
                  + (size_t)m0 * Hn + n0;

    const int r0 = tid >> 3;
    const int cc = (tid & 7) * 4;

    auto fill = [&](int t, int bsel) {
        const uint32_t aOff = sb + bsel * TILE_B;
        const uint32_t bOff = sb + 2 * TILE_B + bsel * TILE_B;
        #pragma unroll
        for (int it = 0; it < 4; it++) {
            int row = r0 + 32 * it;
            cp_async16(aOff + (uint32_t)(row * AROW + cc) * 4,
                       A + (size_t)row * Cn + t * 32 + cc);
            cp_async16(bOff + (uint32_t)(row * AROW + cc) * 4,
                       Bt + (size_t)row * Cn + t * 32 + cc);
        }
    };

    float acc[2][8][4];
    #pragma unroll
    for (int mt = 0; mt < 2; mt++)
        #pragma unroll
        for (int nt = 0; nt < 8; nt++)
            #pragma unroll
            for (int q = 0; q < 4; q++) acc[mt][nt][q] = 0.f;

    fill(0, 0);
    cp_commit();

    const int NT = Cn / 32;
    #pragma unroll 1
    for (int t = 0; t < NT; t++) {
        if (t + 1 < NT) {
            fill(t + 1, (t + 1) & 1);
            cp_commit();
            asm volatile("cp.async.wait_group 1;" ::: "memory");
        } else {
            asm volatile("cp.async.wait_group 0;" ::: "memory");
        }
        __syncthreads();

        const float* As = (const float*)(smem + (t & 1) * TILE_B);
        const float* Bs = (const float*)(smem + 2 * TILE_B + (t & 1) * TILE_B);

        #pragma unroll
        for (int k8 = 0; k8 < 32; k8 += 8) {
            uint32_t a[2][4];
            #pragma unroll
            for (int mt = 0; mt < 2; mt++) {
                int m = wm * 32 + mt * 16 + group;
                a[mt][0] = f2tf32(As[m * AROW + k8 + tig]);
                a[mt][1] = f2tf32(As[(m + 8) * AROW + k8 + tig]);
                a[mt][2] = f2tf32(As[m * AROW + k8 + tig + 4]);
                a[mt][3] = f2tf32(As[(m + 8) * AROW + k8 + tig + 4]);
            }
            uint32_t b[8][2];
            #pragma unroll
            for (int nt = 0; nt < 8; nt++) {
                int n = wn * 64 + nt * 8 + group;
                b[nt][0] = f2tf32(Bs[n * AROW + k8 + tig]);
                b[nt][1] = f2tf32(Bs[n * AROW + k8 + tig + 4]);
            }
            #pragma unroll
            for (int mt = 0; mt < 2; mt++)
                #pragma unroll
                for (int nt = 0; nt < 8; nt++)
                    mma_tf32(acc[mt][nt], a[mt], b[nt]);
        }
        __syncthreads();
    }

    // Epilogue: store tf32-rounded results
    #pragma unroll
    for (int mt = 0; mt < 2; mt++) {
        int m = wm * 32 + mt * 16 + group;
        #pragma unroll
        for (int nt = 0; nt < 8; nt++) {
            int col = wn * 64 + nt * 8 + 2 * tig;
            *(float2*)&outp[(size_t)m * Hn + col] =
                make_float2(__uint_as_float(f2tf32(acc[mt][nt][0])),
                            __uint_as_float(f2tf32(acc[mt][nt][1])));
            *(float2*)&outp[(size_t)(m + 8) * Hn + col] =
                make_float2(__uint_as_float(f2tf32(acc[mt][nt][2])),
                            __uint_as_float(f2tf32(acc[mt][nt][3])));
        }
    }
}

// ---------------------------------------------------------------------------
// Transpose V: [b][T][H] -> g_Vt[b][H][T]
// ---------------------------------------------------------------------------
__global__ __launch_bounds__(256)
void transpose_v_kernel() {
    __shared__ float tile[32][33];
    const int b = blockIdx.z;
    const float* src = g_V  + (size_t)b * Tn * Hn;
    float*       dst = g_Vt + (size_t)b * Hn * Tn;
    const int t0 = blockIdx.x * 32;
    const int d0 = blockIdx.y * 32;
    const int tx = threadIdx.x, ty = threadIdx.y;
    #pragma unroll
    for (int i = 0; i < 4; i++)
        tile[ty + 8 * i][tx] = src[(size_t)(t0 + ty + 8 * i) * Hn + d0 + tx];
    __syncthreads();
    #pragma unroll
    for (int i = 0; i < 4; i++)
        dst[(size_t)(d0 + ty + 8 * i) * Tn + t0 + tx] = tile[tx][ty + 8 * i];
}

// ---------------------------------------------------------------------------
// Causal flash attention on mma.sync tf32.
// BLOCK_M=64 x BLOCK_N=64, 8 warps (wm=warp&3 rows, wn=warp>>2).
// S: warp tile 16x32 (4 n-tiles), K=256 in 32 k8-steps.
// PV: warp tile 16 rows x 128 dims (16 n-tiles), K=64 in 8 k8-steps.
// All smem row strides ≡ 4 (mod 32) words -> conflict-free fragment loads.
// ---------------------------------------------------------------------------
#define PADQ 260
#define PADV 68
#define PADP 68
#define OFF_QS 0
#define OFF_KS (64 * PADQ * 4)
#define OFF_VT (2 * 64 * PADQ * 4)
#define OFF_PS (OFF_VT + 256 * PADV * 4)
#define OFF_RED (OFF_PS + 64 * PADP * 4)
#define ATTN_SMEM (OFF_RED + 2 * 2 * 64 * 4)   // 221184 B

__global__ __launch_bounds__(256, 1)
void attn_mma_kernel(float* __restrict__ out) {
    extern __shared__ char smem[];
    float* Qs = (float*)(smem + OFF_QS);     // [64][260]
    float* Ks = (float*)(smem + OFF_KS);     // [64][260]
    float* Vt = (float*)(smem + OFF_VT);     // [256][68]  (dim-major)
    float* Ps = (float*)(smem + OFF_PS);     // [64][68]
    float* redmax = (float*)(smem + OFF_RED);// [2][64]
    float* redsum = redmax + 128;            // [2][64]

    const int b   = blockIdx.y;
    const int m0  = ((int)gridDim.x - 1 - (int)blockIdx.x) * 64;
    const int tid = threadIdx.x;
    const int warp = tid >> 5, lane = tid & 31;
    const int group = lane >> 2, tig = lane & 3;
    const int wm = warp & 3, wn = warp >> 2;

    const float* Qb  = g_Q  + (size_t)b * Tn * Hn;
    const float* Kb  = g_K  + (size_t)b * Tn * Hn;
    const float* Vtb = g_Vt + (size_t)b * Hn * Tn;

    const float scale = 0.0625f;   // power of 2: tf32-exact

    // Stage Q tile (scaled)
    #pragma unroll
    for (int it = 0; it < 16; it++) {
        int f = tid + it * 256;
        int r = f >> 6, c4 = (f & 63) * 4;
        float4 v = *(const float4*)&Qb[(size_t)(m0 + r) * Hn + c4];
        v.x *= scale; v.y *= scale; v.z *= scale; v.w *= scale;
        *(float4*)&Qs[r * PADQ + c4] = v;
    }

    const int r0 = wm * 16 + group;          // owned rows: r0, r0+8
    float m_run0 = -INFINITY, m_run1 = -INFINITY;
    float l_run0 = 0.f, l_run1 = 0.f;
    float o[16][4];
    #pragma unroll
    for (int nt = 0; nt < 16; nt++)
        #pragma unroll
        for (int q = 0; q < 4; q++) o[nt][q] = 0.f;

    #pragma unroll 1
    for (int kv0 = 0; kv0 <= m0; kv0 += 64) {
        __syncthreads();   // previous iteration's Ks/Vt/Ps reads complete
        // Stage K tile
        #pragma unroll
        for (int it = 0; it < 16; it++) {
            int f = tid + it * 256;
            int r = f >> 6, c4 = (f & 63) * 4;
            *(float4*)&Ks[r * PADQ + c4] =
                *(const float4*)&Kb[(size_t)(kv0 + r) * Hn + c4];
        }
        // Stage Vt tile (dim-major)
        #pragma unroll
        for (int it = 0; it < 16; it++) {
            int f = tid + it * 256;
            int d = f >> 4, c4 = (f & 15) * 4;
            *(float4*)&Vt[d * PADV + c4] =
                *(const float4*)&Vtb[(size_t)d * Tn + kv0 + c4];
        }
        __syncthreads();

        // ---- S = Q K^T ----
        float sacc[4][4];
        #pragma unroll
        for (int nt = 0; nt < 4; nt++)
            #pragma unroll
            for (int q = 0; q < 4; q++) sacc[nt][q] = 0.f;

        #pragma unroll
        for (int k8 = 0; k8 < 256; k8 += 8) {
            uint32_t a[4];
            a[0] = __float_as_uint(Qs[r0 * PADQ + k8 + tig]);
            a[1] = __float_as_uint(Qs[(r0 + 8) * PADQ + k8 + tig]);
            a[2] = __float_as_uint(Qs[r0 * PADQ + k8 + tig + 4]);
            a[3] = __float_as_uint(Qs[(r0 + 8) * PADQ + k8 + tig + 4]);
            #pragma unroll
            for (int nt = 0; nt < 4; nt++) {
                int n = wn * 32 + nt * 8 + group;
                uint32_t bb[2];
                bb[0] = __float_as_uint(Ks[n * PADQ + k8 + tig]);
                bb[1] = __float_as_uint(Ks[n * PADQ + k8 + tig + 4]);
                mma_tf32(sacc[nt], a, bb);
            }
        }

        // ---- causal mask + row max ----
        const int row0 = m0 + r0, row1 = row0 + 8;
        float mx0 = -INFINITY, mx1 = -INFINITY;
        #pragma unroll
        for (int nt = 0; nt < 4; nt++) {
            int cb = kv0 + wn * 32 + nt * 8 + 2 * tig;
            if (cb     > row0) sacc[nt][0] = -INFINITY;
            if (cb + 1 > row0) sacc[nt][1] = -INFINITY;
            if (cb     > row1) sacc[nt][2] = -INFINITY;
            if (cb + 1 > row1) sacc[nt][3] = -INFINITY;
            mx0 = fmaxf(mx0, fmaxf(sacc[nt][0], sacc[nt][1]));
            mx1 = fmaxf(mx1, fmaxf(sacc[nt][2], sacc[nt][3]));
        }
        mx0 = fmaxf(mx0, __shfl_xor_sync(0xffffffffu, mx0, 1));
        mx0 = fmaxf(mx0, __shfl_xor_sync(0xffffffffu, mx0, 2));
        mx1 = fmaxf(mx1, __shfl_xor_sync(0xffffffffu, mx1, 1));
        mx1 = fmaxf(mx1, __shfl_xor_sync(0xffffffffu, mx1, 2));
        if (tig == 0) {
            redmax[wn * 64 + r0]     = mx0;
            redmax[wn * 64 + r0 + 8] = mx1;
        }
        __syncthreads();
        float tm0 = fmaxf(redmax[r0],     redmax[64 + r0]);
        float tm1 = fmaxf(redmax[r0 + 8], redmax[64 + r0 + 8]);
        float mnew0 = fmaxf(m_run0, tm0), mnew1 = fmaxf(m_run1, tm1);
        float alpha0 = __expf(m_run0 - mnew0), alpha1 = __expf(m_run1 - mnew1);
        m_run0 = mnew0; m_run1 = mnew1;

        // ---- exp, P write (tf32-rounded), row sum ----
        float ps0 = 0.f, ps1 = 0.f;
        #pragma unroll
        for (int nt = 0; nt < 4; nt++) {
            int cl = wn * 32 + nt * 8 + 2 * tig;
            float e0 = __expf(sacc[nt][0] - mnew0);
            float e1 = __expf(sacc[nt][1] - mnew0);
            float e2 = __expf(sacc[nt][2] - mnew1);
            float e3 = __expf(sacc[nt][3] - mnew1);
            ps0 += e0 + e1; ps1 += e2 + e3;
            *(float2*)&Ps[r0 * PADP + cl] =
                make_float2(__uint_as_float(f2tf32(e0)), __uint_as_float(f2tf32(e1)));
            *(float2*)&Ps[(r0 + 8) * PADP + cl] =
                make_float2(__uint_as_float(f2tf32(e2)), __uint_as_float(f2tf32(e3)));
        }
        ps0 += __shfl_xor_sync(0xffffffffu, ps0, 1);
        ps0 += __shfl_xor_sync(0xffffffffu, ps0, 2);
        ps1 += __shfl_xor_sync(0xffffffffu, ps1, 1);
        ps1 += __shfl_xor_sync(0xffffffffu, ps1, 2);
        if (tig == 0) {
            redsum[wn * 64 + r0]     = ps0;
            redsum[wn * 64 + r0 + 8] = ps1;
        }
        __syncthreads();
        l_run0 = l_run0 * alpha0 + redsum[r0]     + redsum[64 + r0];
        l_run1 = l_run1 * alpha1 + redsum[r0 + 8] + redsum[64 + r0 + 8];

        // ---- rescale O ----
        #pragma unroll
        for (int nt = 0; nt < 16; nt++) {
            o[nt][0] *= alpha0; o[nt][1] *= alpha0;
            o[nt][2] *= alpha1; o[nt][3] *= alpha1;
        }

        // ---- O += P V ----
        #pragma unroll
        for (int k8 = 0; k8 < 64; k8 += 8) {
            uint32_t a[4];
            a[0] = __float_as_uint(Ps[r0 * PADP + k8 + tig]);
            a[1] = __float_as_uint(Ps[(r0 + 8) * PADP + k8 + tig]);
            a[2] = __float_as_uint(Ps[r0 * PADP + k8 + tig + 4]);
            a[3] = __float_as_uint(Ps[(r0 + 8) * PADP + k8 + tig + 4]);
            #pragma unroll
            for (int nt = 0; nt < 16; nt++) {
                int n = wn * 128 + nt * 8 + group;
                uint32_t bb[2];
                bb[0] = __float_as_uint(Vt[n * PADV + k8 + tig]);
                bb[1] = __float_as_uint(Vt[n * PADV + k8 + tig + 4]);
                mma_tf32(o[nt], a, bb);
            }
        }
    }

    // ---- epilogue ----
    float inv0 = 1.f / l_run0, inv1 = 1.f / l_run1;
    float* ob = out + ((size_t)b * Tn + m0) * Hn;
    #pragma unroll
    for (int nt = 0; nt < 16; nt++) {
        int col = wn * 128 + nt * 8 + 2 * tig;
        *(float2*)&ob[(size_t)r0 * Hn + col] =
            make_float2(o[nt][0] * inv0, o[nt][1] * inv0);
        *(float2*)&ob[(size_t)(r0 + 8) * Hn + col] =
            make_float2(o[nt][2] * inv1, o[nt][3] * inv1);
    }
}

extern "C" void kernel_launch(void* const* d_in, const int* in_sizes, int n_in,
                              void* d_out, int out_size) {
    const float* x  = (const float*)d_in[0];
    const float* Wq = (const float*)d_in[1];
    const float* Wk = (const float*)d_in[2];
    const float* Wv = (const float*)d_in[3];
    float* out = (float*)d_out;

    transpose_w_kernel<<<dim3(Cn / 32, Hn / 32, 3), dim3(32, 8)>>>(Wq, Wk, Wv);

    cudaFuncSetAttribute(proj_wmma_kernel,
                         cudaFuncAttributeMaxDynamicSharedMemorySize, PROJ_SMEM);
    proj_wmma_kernel<<<dim3(Mn / 128, Hn / 128, 3), 256, PROJ_SMEM>>>(x);

    transpose_v_kernel<<<dim3(Tn / 32, Hn / 32, Bn), dim3(32, 8)>>>();

    cudaFuncSetAttribute(attn_mma_kernel,
                         cudaFuncAttributeMaxDynamicSharedMemorySize, ATTN_SMEM);
    attn_mma_kernel<<<dim3(Tn / 64, Bn), 256, ATTN_SMEM>>>(out);
}

// round 7
// speedup vs baseline: 15.4296x; 1.0865x over previous
#include <cuda_runtime.h>
#include <math.h>
#include <cstdint>

#define Bn 8
#define Tn 2048
#define Cn 1024
#define Hn 256
#define Mn (Bn * Tn)   // 16384

// Scratch (allocation-free rule: __device__ globals)
__device__ float g_Q[Mn * Hn];       // [b][T][H]  (tf32-rounded)
__device__ float g_K[Mn * Hn];       // [b][T][H]  (tf32-rounded)
__device__ float g_V[Mn * Hn];       // [b][T][H]  (tf32-rounded)
__device__ float g_Vp[Mn * Hn];      // packed PV B-fragments per 32-key block
__device__ float g_Wt[3 * Hn * Cn];  // [which][n][k]

// ---------------------------------------------------------------------------
// Helpers
// ---------------------------------------------------------------------------
__device__ __forceinline__ uint32_t smem_u32(const void* p) {
    uint32_t a;
    asm("{ .reg .u64 t; cvta.to.shared.u64 t, %1; cvt.u32.u64 %0, t; }"
        : "=r"(a) : "l"(p));
    return a;
}
__device__ __forceinline__ uint32_t f2tf32(float f) {
    uint32_t u;
    asm("cvt.rna.tf32.f32 %0, %1;" : "=r"(u) : "f"(f));
    return u;
}
__device__ __forceinline__ void cp_async16(uint32_t saddr, const void* g) {
    asm volatile("cp.async.cg.shared.global [%0], [%1], 16;"
                 :: "r"(saddr), "l"(g) : "memory");
}
__device__ __forceinline__ void cp_commit() {
    asm volatile("cp.async.commit_group;" ::: "memory");
}
__device__ __forceinline__ void mma_tf32(float* c, const uint32_t* a, const uint32_t* b) {
    asm volatile(
        "mma.sync.aligned.m16n8k8.row.col.f32.tf32.tf32.f32 "
        "{%0,%1,%2,%3}, {%4,%5,%6,%7}, {%8,%9}, {%0,%1,%2,%3};"
        : "+f"(c[0]), "+f"(c[1]), "+f"(c[2]), "+f"(c[3])
        : "r"(a[0]), "r"(a[1]), "r"(a[2]), "r"(a[3]), "r"(b[0]), "r"(b[1]));
}

// ---------------------------------------------------------------------------
// Transpose W: [K=1024, N=256] -> g_Wt[which][N][K]
// ---------------------------------------------------------------------------
__global__ __launch_bounds__(256)
void transpose_w_kernel(const float* __restrict__ Wq,
                        const float* __restrict__ Wk,
                        const float* __restrict__ Wv) {
    __shared__ float tile[32][33];
    const int which = blockIdx.z;
    const float* W = (which == 0) ? Wq : (which == 1 ? Wk : Wv);
    float* dst = g_Wt + (size_t)which * Hn * Cn;
    const int k0 = blockIdx.x * 32;
    const int n0 = blockIdx.y * 32;
    const int tx = threadIdx.x, ty = threadIdx.y;
    #pragma unroll
    for (int i = 0; i < 4; i++)
        tile[ty + 8 * i][tx] = W[(size_t)(k0 + ty + 8 * i) * Hn + n0 + tx];
    __syncthreads();
    #pragma unroll
    for (int i = 0; i < 4; i++)
        dst[(size_t)(n0 + ty + 8 * i) * Cn + k0 + tx] = tile[tx][ty + 8 * i];
}

// ---------------------------------------------------------------------------
// Projection via mma.sync tf32; outputs tf32-ROUNDED fp32.
// ---------------------------------------------------------------------------
#define AROW 36
#define TILE_F (128 * AROW)
#define TILE_B (TILE_F * 4)
#define PROJ_SMEM (4 * TILE_B)

__global__ __launch_bounds__(256, 2)
void proj_wmma_kernel(const float* __restrict__ x) {
    extern __shared__ char smem[];
    const uint32_t sb = smem_u32(smem);

    const int tid  = threadIdx.x;
    const int warp = tid >> 5, lane = tid & 31;
    const int group = lane >> 2, tig = lane & 3;
    const int wm = warp & 3, wn = warp >> 2;
    const int which = blockIdx.z;
    const int m0 = blockIdx.x * 128, n0 = blockIdx.y * 128;

    const float* A  = x + (size_t)m0 * Cn;
    const float* Bt = g_Wt + (size_t)which * Hn * Cn + (size_t)n0 * Cn;
    float* outp = ((which == 0) ? g_Q : (which == 1 ? g_K : g_V))
                  + (size_t)m0 * Hn + n0;

    const int r0 = tid >> 3;
    const int cc = (tid & 7) * 4;

    auto fill = [&](int t, int bsel) {
        const uint32_t aOff = sb + bsel * TILE_B;
        const uint32_t bOff = sb + 2 * TILE_B + bsel * TILE_B;
        #pragma unroll
        for (int it = 0; it < 4; it++) {
            int row = r0 + 32 * it;
            cp_async16(aOff + (uint32_t)(row * AROW + cc) * 4,
                       A + (size_t)row * Cn + t * 32 + cc);
            cp_async16(bOff + (uint32_t)(row * AROW + cc) * 4,
                       Bt + (size_t)row * Cn + t * 32 + cc);
        }
    };

    float acc[2][8][4];
    #pragma unroll
    for (int mt = 0; mt < 2; mt++)
        #pragma unroll
        for (int nt = 0; nt < 8; nt++)
            #pragma unroll
            for (int q = 0; q < 4; q++) acc[mt][nt][q] = 0.f;

    fill(0, 0);
    cp_commit();

    const int NT = Cn / 32;
    #pragma unroll 1
    for (int t = 0; t < NT; t++) {
        if (t + 1 < NT) {
            fill(t + 1, (t + 1) & 1);
            cp_commit();
            asm volatile("cp.async.wait_group 1;" ::: "memory");
        } else {
            asm volatile("cp.async.wait_group 0;" ::: "memory");
        }
        __syncthreads();

        const float* As = (const float*)(smem + (t & 1) * TILE_B);
        const float* Bs = (const float*)(smem + 2 * TILE_B + (t & 1) * TILE_B);

        #pragma unroll
        for (int k8 = 0; k8 < 32; k8 += 8) {
            uint32_t a[2][4];
            #pragma unroll
            for (int mt = 0; mt < 2; mt++) {
                int m = wm * 32 + mt * 16 + group;
                a[mt][0] = f2tf32(As[m * AROW + k8 + tig]);
                a[mt][1] = f2tf32(As[(m + 8) * AROW + k8 + tig]);
                a[mt][2] = f2tf32(As[m * AROW + k8 + tig + 4]);
                a[mt][3] = f2tf32(As[(m + 8) * AROW + k8 + tig + 4]);
            }
            uint32_t b[8][2];
            #pragma unroll
            for (int nt = 0; nt < 8; nt++) {
                int n = wn * 64 + nt * 8 + group;
                b[nt][0] = f2tf32(Bs[n * AROW + k8 + tig]);
                b[nt][1] = f2tf32(Bs[n * AROW + k8 + tig + 4]);
            }
            #pragma unroll
            for (int mt = 0; mt < 2; mt++)
                #pragma unroll
                for (int nt = 0; nt < 8; nt++)
                    mma_tf32(acc[mt][nt], a[mt], b[nt]);
        }
        __syncthreads();
    }

    #pragma unroll
    for (int mt = 0; mt < 2; mt++) {
        int m = wm * 32 + mt * 16 + group;
        #pragma unroll
        for (int nt = 0; nt < 8; nt++) {
            int col = wn * 64 + nt * 8 + 2 * tig;
            *(float2*)&outp[(size_t)m * Hn + col] =
                make_float2(__uint_as_float(f2tf32(acc[mt][nt][0])),
                            __uint_as_float(f2tf32(acc[mt][nt][1])));
            *(float2*)&outp[(size_t)(m + 8) * Hn + col] =
                make_float2(__uint_as_float(f2tf32(acc[mt][nt][2])),
                            __uint_as_float(f2tf32(acc[mt][nt][3])));
        }
    }
}

// ---------------------------------------------------------------------------
// Pack V into PV B-fragment order, per 32-key block.
// Layout per block (32KB): [k8i(4)][wn(2)][ntp(8)][lane(32)][4 floats]
//   c=0: V[key=k8i*8+tig    ][dim=wn*128+2*ntp*8+group]
//   c=1: V[key=k8i*8+tig+4  ][same dim]
//   c=2: V[key=k8i*8+tig    ][dim+8]
//   c=3: V[key=k8i*8+tig+4  ][dim+8]
// ---------------------------------------------------------------------------
__global__ __launch_bounds__(256)
void pack_v_kernel() {
    __shared__ float vs[32][260];
    const int b   = blockIdx.y;
    const int t0  = blockIdx.x * 32;
    const int tid = threadIdx.x;
    const float* src = g_V + ((size_t)b * Tn + t0) * Hn;
    float* dst = g_Vp + ((size_t)b * (Tn / 32) + blockIdx.x) * (32 * 256);

    #pragma unroll
    for (int it = 0; it < 8; it++) {
        int f = tid + it * 256;
        int r = f >> 6, c4 = (f & 63) * 4;
        *(float4*)&vs[r][c4] = *(const float4*)&src[(size_t)r * Hn + c4];
    }
    __syncthreads();

    #pragma unroll
    for (int it = 0; it < 8; it++) {
        int f = tid + it * 256;
        int k8i = f >> 9, wn = (f >> 8) & 1, ntp = (f >> 5) & 7, lane = f & 31;
        int group = lane >> 2, tig = lane & 3;
        int k0 = k8i * 8 + tig, k1 = k0 + 4;
        int d0 = wn * 128 + 2 * ntp * 8 + group, d1 = d0 + 8;
        *(float4*)&dst[(size_t)f * 4] =
            make_float4(vs[k0][d0], vs[k1][d0], vs[k0][d1], vs[k1][d1]);
    }
}

// ---------------------------------------------------------------------------
// Causal flash attention on mma.sync tf32, cp.async double-buffered.
// BLOCK_M=64 queries, BLOCK_N=32 keys/tile, 8 warps (wm 0..3, wn 0..1).
// S: warp 16x16 (2 n-tiles), K=256. PV: warp 16 rows x 128 dims (16 n-tiles),
// V from packed fragments (LDS.128). Softmax barriers narrowed to wm-group.
// ---------------------------------------------------------------------------
#define PADQ 260
#define PADP 36
#define KBUF (32 * PADQ * 4)          // 33280
#define VBUF (32 * 256 * 4)           // 32768
#define OFF_QS 0
#define OFF_KS (64 * PADQ * 4)        // 66560
#define OFF_VP (OFF_KS + 2 * KBUF)    // 133120
#define OFF_PS (OFF_VP + 2 * VBUF)    // 198656
#define OFF_RED (OFF_PS + 64 * PADP * 4)  // 207872
#define ATTN_SMEM (OFF_RED + 2 * 2 * 64 * 4)  // 208896

__global__ __launch_bounds__(256, 1)
void attn_mma_kernel(float* __restrict__ out) {
    extern __shared__ char smem[];
    const uint32_t sb = smem_u32(smem);
    float* Qs = (float*)(smem + OFF_QS);      // [64][260]
    float* Ps = (float*)(smem + OFF_PS);      // [64][36]
    float* redmax = (float*)(smem + OFF_RED); // [2][64]
    float* redsum = redmax + 128;             // [2][64]

    const int b   = blockIdx.y;
    const int m0  = ((int)gridDim.x - 1 - (int)blockIdx.x) * 64;
    const int tid = threadIdx.x;
    const int warp = tid >> 5, lane = tid & 31;
    const int group = lane >> 2, tig = lane & 3;
    const int wm = warp & 3, wn = warp >> 2;

    const float* Qb  = g_Q + ((size_t)b * Tn + m0) * Hn;
    const float* Kb  = g_K + (size_t)b * Tn * Hn;
    const float* Vpb = g_Vp + (size_t)b * (Tn / 32) * (32 * 256);

    const float scale = 0.0625f;

    // Fill K tile t into buffer bs (natural padded), V packed block
    auto fillKV = [&](int t, int bs) {
        const uint32_t kOff = sb + OFF_KS + bs * KBUF;
        const float* Kg = Kb + (size_t)t * 32 * Hn;
        #pragma unroll
        for (int it = 0; it < 8; it++) {
            int f = tid + it * 256;
            int r = f >> 6, c4 = (f & 63) * 4;
            cp_async16(kOff + (uint32_t)(r * PADQ + c4) * 4,
                       Kg + (size_t)r * Hn + c4);
        }
        const uint32_t vOff = sb + OFF_VP + bs * VBUF;
        const float* Vg = Vpb + (size_t)t * (32 * 256);
        #pragma unroll
        for (int it = 0; it < 8; it++) {
            int f = tid + it * 256;
            cp_async16(vOff + (uint32_t)f * 16, Vg + (size_t)f * 4);
        }
    };

    // Stage Q (raw; scale applied post-GEMM) + first K/V, one commit group
    #pragma unroll
    for (int it = 0; it < 16; it++) {
        int f = tid + it * 256;
        int r = f >> 6, c4 = (f & 63) * 4;
        cp_async16(sb + OFF_QS + (uint32_t)(r * PADQ + c4) * 4,
                   Qb + (size_t)r * Hn + c4);
    }
    fillKV(0, 0);
    cp_commit();

    const int r0 = wm * 16 + group;           // owned rows r0, r0+8
    float m_run0 = -INFINITY, m_run1 = -INFINITY;
    float l_run0 = 0.f, l_run1 = 0.f;
    float o[16][4];
    #pragma unroll
    for (int nt = 0; nt < 16; nt++)
        #pragma unroll
        for (int q = 0; q < 4; q++) o[nt][q] = 0.f;

    const int NT = m0 / 32 + 2;
    #pragma unroll 1
    for (int t = 0; t < NT; t++) {
        if (t + 1 < NT) {
            fillKV(t + 1, (t + 1) & 1);
            cp_commit();
            asm volatile("cp.async.wait_group 1;" ::: "memory");
        } else {
            asm volatile("cp.async.wait_group 0;" ::: "memory");
        }
        __syncthreads();

        const float* Ks = (const float*)(smem + OFF_KS + (t & 1) * KBUF);
        const float4* Vp4 = (const float4*)(smem + OFF_VP + (t & 1) * VBUF);
        const int kv0 = t * 32;

        // ---- S = Q K^T (2 n-tiles per warp) ----
        float sacc[2][4];
        #pragma unroll
        for (int nt = 0; nt < 2; nt++)
            #pragma unroll
            for (int q = 0; q < 4; q++) sacc[nt][q] = 0.f;

        #pragma unroll
        for (int k8 = 0; k8 < 256; k8 += 8) {
            uint32_t a[4];
            a[0] = __float_as_uint(Qs[r0 * PADQ + k8 + tig]);
            a[1] = __float_as_uint(Qs[(r0 + 8) * PADQ + k8 + tig]);
            a[2] = __float_as_uint(Qs[r0 * PADQ + k8 + tig + 4]);
            a[3] = __float_as_uint(Qs[(r0 + 8) * PADQ + k8 + tig + 4]);
            #pragma unroll
            for (int nt = 0; nt < 2; nt++) {
                int n = wn * 16 + nt * 8 + group;
                uint32_t bb[2];
                bb[0] = __float_as_uint(Ks[n * PADQ + k8 + tig]);
                bb[1] = __float_as_uint(Ks[n * PADQ + k8 + tig + 4]);
                mma_tf32(sacc[nt], a, bb);
            }
        }

        // ---- scale + causal mask + row max ----
        const int row0 = m0 + r0, row1 = row0 + 8;
        float mx0 = -INFINITY, mx1 = -INFINITY;
        #pragma unroll
        for (int nt = 0; nt < 2; nt++) {
            int cb = kv0 + wn * 16 + nt * 8 + 2 * tig;
            sacc[nt][0] = (cb     <= row0) ? sacc[nt][0] * scale : -INFINITY;
            sacc[nt][1] = (cb + 1 <= row0) ? sacc[nt][1] * scale : -INFINITY;
            sacc[nt][2] = (cb     <= row1) ? sacc[nt][2] * scale : -INFINITY;
            sacc[nt][3] = (cb + 1 <= row1) ? sacc[nt][3] * scale : -INFINITY;
            mx0 = fmaxf(mx0, fmaxf(sacc[nt][0], sacc[nt][1]));
            mx1 = fmaxf(mx1, fmaxf(sacc[nt][2], sacc[nt][3]));
        }
        mx0 = fmaxf(mx0, __shfl_xor_sync(0xffffffffu, mx0, 1));
        mx0 = fmaxf(mx0, __shfl_xor_sync(0xffffffffu, mx0, 2));
        mx1 = fmaxf(mx1, __shfl_xor_sync(0xffffffffu, mx1, 1));
        mx1 = fmaxf(mx1, __shfl_xor_sync(0xffffffffu, mx1, 2));
        if (tig == 0) {
            redmax[wn * 64 + r0]     = mx0;
            redmax[wn * 64 + r0 + 8] = mx1;
        }
        asm volatile("bar.sync %0, 64;" :: "r"(1 + wm) : "memory");
        float mnew0 = fmaxf(m_run0, fmaxf(redmax[r0],     redmax[64 + r0]));
        float mnew1 = fmaxf(m_run1, fmaxf(redmax[r0 + 8], redmax[64 + r0 + 8]));
        float alpha0 = __expf(m_run0 - mnew0), alpha1 = __expf(m_run1 - mnew1);
        m_run0 = mnew0; m_run1 = mnew1;

        // ---- exp, P write (tf32-rounded), row sum ----
        float ps0 = 0.f, ps1 = 0.f;
        #pragma unroll
        for (int nt = 0; nt < 2; nt++) {
            int cl = wn * 16 + nt * 8 + 2 * tig;
            float e0 = __expf(sacc[nt][0] - mnew0);
            float e1 = __expf(sacc[nt][1] - mnew0);
            float e2 = __expf(sacc[nt][2] - mnew1);
            float e3 = __expf(sacc[nt][3] - mnew1);
            ps0 += e0 + e1; ps1 += e2 + e3;
            *(float2*)&Ps[r0 * PADP + cl] =
                make_float2(__uint_as_float(f2tf32(e0)), __uint_as_float(f2tf32(e1)));
            *(float2*)&Ps[(r0 + 8) * PADP + cl] =
                make_float2(__uint_as_float(f2tf32(e2)), __uint_as_float(f2tf32(e3)));
        }
        ps0 += __shfl_xor_sync(0xffffffffu, ps0, 1);
        ps0 += __shfl_xor_sync(0xffffffffu, ps0, 2);
        ps1 += __shfl_xor_sync(0xffffffffu, ps1, 1);
        ps1 += __shfl_xor_sync(0xffffffffu, ps1, 2);
        if (tig == 0) {
            redsum[wn * 64 + r0]     = ps0;
            redsum[wn * 64 + r0 + 8] = ps1;
        }
        asm volatile("bar.sync %0, 64;" :: "r"(1 + wm) : "memory");
        l_run0 = l_run0 * alpha0 + redsum[r0]     + redsum[64 + r0];
        l_run1 = l_run1 * alpha1 + redsum[r0 + 8] + redsum[64 + r0 + 8];

        // ---- rescale O ----
        #pragma unroll
        for (int nt = 0; nt < 16; nt++) {
            o[nt][0] *= alpha0; o[nt][1] *= alpha0;
            o[nt][2] *= alpha1; o[nt][3] *= alpha1;
        }

        // ---- O += P V (V fragments packed: LDS.128) ----
        #pragma unroll
        for (int k8i = 0; k8i < 4; k8i++) {
            int k8 = k8i * 8;
            uint32_t a[4];
            a[0] = __float_as_uint(Ps[r0 * PADP + k8 + tig]);
            a[1] = __float_as_uint(Ps[(r0 + 8) * PADP + k8 + tig]);
            a[2] = __float_as_uint(Ps[r0 * PADP + k8 + tig + 4]);
            a[3] = __float_as_uint(Ps[(r0 + 8) * PADP + k8 + tig + 4]);
            #pragma unroll
            for (int ntp = 0; ntp < 8; ntp++) {
                float4 bv = Vp4[((k8i * 2 + wn) * 8 + ntp) * 32 + lane];
                uint32_t b0[2] = {__float_as_uint(bv.x), __float_as_uint(bv.y)};
                uint32_t b1[2] = {__float_as_uint(bv.z), __float_as_uint(bv.w)};
                mma_tf32(o[2 * ntp],     a, b0);
                mma_tf32(o[2 * ntp + 1], a, b1);
            }
        }
        __syncthreads();
    }

    // ---- epilogue ----
    float inv0 = 1.f / l_run0, inv1 = 1.f / l_run1;
    float* ob = out + ((size_t)b * Tn + m0) * Hn;
    #pragma unroll
    for (int nt = 0; nt < 16; nt++) {
        int col = wn * 128 + nt * 8 + 2 * tig;
        *(float2*)&ob[(size_t)r0 * Hn + col] =
            make_float2(o[nt][0] * inv0, o[nt][1] * inv0);
        *(float2*)&ob[(size_t)(r0 + 8) * Hn + col] =
            make_float2(o[nt][2] * inv1, o[nt][3] * inv1);
    }
}

extern "C" void kernel_launch(void* const* d_in, const int* in_sizes, int n_in,
                              void* d_out, int out_size) {
    const float* x  = (const float*)d_in[0];
    const float* Wq = (const float*)d_in[1];
    const float* Wk = (const float*)d_in[2];
    const float* Wv = (const float*)d_in[3];
    float* out = (float*)d_out;

    transpose_w_kernel<<<dim3(Cn / 32, Hn / 32, 3), dim3(32, 8)>>>(Wq, Wk, Wv);

    cudaFuncSetAttribute(proj_wmma_kernel,
                         cudaFuncAttributeMaxDynamicSharedMemorySize, PROJ_SMEM);
    proj_wmma_kernel<<<dim3(Mn / 128, Hn / 128, 3), 256, PROJ_SMEM>>>(x);

    pack_v_kernel<<<dim3(Tn / 32, Bn), 256>>>();

    cudaFuncSetAttribute(attn_mma_kernel,
                         cudaFuncAttributeMaxDynamicSharedMemorySize, ATTN_SMEM);
    attn_mma_kernel<<<dim3(Tn / 64, Bn), 256, ATTN_SMEM>>>(out);
}